// round 4
// baseline (speedup 1.0000x reference)
#include <cuda_runtime.h>
#include <math.h>

// Problem constants
#define Wn  8
#define En  4
#define Cn  2048
#define Hn  1024
#define Dff 4096

// 1 GiB scratch for the gelu(x@W1+b1) intermediate: [W, E, C, DFF] fp32.
// __device__ global array: allocation-free per harness rules.
__device__ float g_h[(size_t)Wn * En * Cn * Dff];

// ---------------------------------------------------------------------------
// Packed fp32x2 helpers (FFMA2 path; only reachable via PTX fma.rn.f32x2)
// ---------------------------------------------------------------------------
__device__ __forceinline__ unsigned long long bcast2(float x) {
    unsigned long long r;
    asm("mov.b64 %0, {%1, %1};" : "=l"(r) : "f"(x));
    return r;
}
__device__ __forceinline__ void ffma2(unsigned long long& d,
                                      unsigned long long a,
                                      unsigned long long b) {
    asm("fma.rn.f32x2 %0, %1, %2, %0;" : "+l"(d) : "l"(a), "l"(b));
}
__device__ __forceinline__ void unpack2(unsigned long long v, float& x, float& y) {
    asm("mov.b64 {%0, %1}, %2;" : "=f"(x), "=f"(y) : "l"(v));
}

// JAX default gelu (approximate=True, tanh form)
__device__ __forceinline__ float gelu_tanh(float x) {
    float x3 = x * x * x;
    float t  = tanhf(0.7978845608028654f * (x + 0.044715f * x3));
    return 0.5f * x * (1.0f + t);
}

// ---------------------------------------------------------------------------
// Grouped GEMM:  C[z] = act( A[z] (Cn x KDIM)  @  B[e] (KDIM x NDIM) + bias[e] )
//   z in [0, W*E), e = z % E.  All dims divide the tile sizes exactly.
// Tiling: BM=BN=128, BK=8; 256 threads; 8x8 microtile per thread.
// Inner product issued as packed f32x2 FMAs (2 MACs / issue slot).
// ---------------------------------------------------------------------------
template <int KDIM, int NDIM, bool GELU, bool A_SCRATCH, bool C_SCRATCH>
__global__ void __launch_bounds__(256, 2)
moe_gemm(const float* __restrict__ Aall, const float* __restrict__ Ball,
         const float* __restrict__ biasAll, float* __restrict__ Call) {
    constexpr int BM = 128, BN = 128, BK = 8;

    const int z = blockIdx.z;
    const int e = z & (En - 1);

    const float* A = A_SCRATCH ? ((const float*)g_h + (size_t)z * Cn * KDIM)
                               : (Aall + (size_t)z * Cn * KDIM);
    const float* B    = Ball    + (size_t)e * KDIM * NDIM;
    const float* bias = biasAll + (size_t)e * NDIM;
    float* Cp = C_SCRATCH ? (g_h + (size_t)z * Cn * NDIM)
                          : (Call + (size_t)z * Cn * NDIM);

    __shared__ __align__(16) float As[BK][BM];  // A tile stored transposed
    __shared__ __align__(16) float Bs[BK][BN];

    const int tid = threadIdx.x;
    const int m0  = blockIdx.y * BM;
    const int n0  = blockIdx.x * BN;

    // Global load mapping
    const int arow = tid >> 1;          // 0..127
    const int acol = (tid & 1) * 4;     // 0 or 4 (within BK=8)
    const int brow = tid >> 5;          // 0..7
    const int bcol = (tid & 31) * 4;    // 0..124

    // Compute mapping: 16x16 thread grid of 8x8 microtiles
    const int ty = tid >> 4;            // 0..15 -> rows  ty*8..
    const int tx = tid & 15;            // 0..15 -> cols  tx*8..

    unsigned long long acc[8][4];       // 8 rows x 4 f32x2 pairs (= 8 cols)
#pragma unroll
    for (int i = 0; i < 8; ++i)
#pragma unroll
        for (int j = 0; j < 4; ++j) acc[i][j] = 0ull;

    const float* Aptr = A + (size_t)(m0 + arow) * KDIM + acol;
    const float* Bptr = B + (size_t)brow * NDIM + n0 + bcol;

    float4 aReg = *(const float4*)Aptr;
    float4 bReg = *(const float4*)Bptr;

    const int ktiles = KDIM / BK;
    for (int t = 0; t < ktiles; ++t) {
        // Stage current tile into shared memory (A transposed)
        As[acol + 0][arow] = aReg.x;
        As[acol + 1][arow] = aReg.y;
        As[acol + 2][arow] = aReg.z;
        As[acol + 3][arow] = aReg.w;
        *(float4*)&Bs[brow][bcol] = bReg;
        __syncthreads();

        // Prefetch next tile (hidden behind the compute below)
        if (t + 1 < ktiles) {
            aReg = *(const float4*)(Aptr + (size_t)(t + 1) * BK);
            bReg = *(const float4*)(Bptr + (size_t)(t + 1) * BK * NDIM);
        }

#pragma unroll
        for (int k = 0; k < BK; ++k) {
            float4 a0 = *(const float4*)&As[k][ty * 8];
            float4 a1 = *(const float4*)&As[k][ty * 8 + 4];
            ulonglong2 b01 = *(const ulonglong2*)&Bs[k][tx * 8];
            ulonglong2 b23 = *(const ulonglong2*)&Bs[k][tx * 8 + 4];
            const unsigned long long bp0 = b01.x, bp1 = b01.y;
            const unsigned long long bp2 = b23.x, bp3 = b23.y;
            const float av[8] = {a0.x, a0.y, a0.z, a0.w, a1.x, a1.y, a1.z, a1.w};
#pragma unroll
            for (int i = 0; i < 8; ++i) {
                const unsigned long long ap = bcast2(av[i]);
                ffma2(acc[i][0], ap, bp0);
                ffma2(acc[i][1], ap, bp1);
                ffma2(acc[i][2], ap, bp2);
                ffma2(acc[i][3], ap, bp3);
            }
        }
        __syncthreads();
    }

    // Epilogue: bias (+ gelu), vectorized stores
    const int gm = m0 + ty * 8;
    const int gn = n0 + tx * 8;
    float bv[8];
#pragma unroll
    for (int j = 0; j < 8; ++j) bv[j] = bias[gn + j];

#pragma unroll
    for (int i = 0; i < 8; ++i) {
        float o[8];
#pragma unroll
        for (int j = 0; j < 4; ++j) unpack2(acc[i][j], o[2 * j], o[2 * j + 1]);
#pragma unroll
        for (int j = 0; j < 8; ++j) {
            float v = o[j] + bv[j];
            if (GELU) v = gelu_tanh(v);
            o[j] = v;
        }
        float* crow = Cp + (size_t)(gm + i) * NDIM + gn;
        *(float4*)(crow)     = make_float4(o[0], o[1], o[2], o[3]);
        *(float4*)(crow + 4) = make_float4(o[4], o[5], o[6], o[7]);
    }
}

extern "C" void kernel_launch(void* const* d_in, const int* in_sizes, int n_in,
                              void* d_out, int out_size) {
    const float* x  = (const float*)d_in[0];  // [W, E, C, H]
    const float* W1 = (const float*)d_in[1];  // [E, H, DFF]
    const float* b1 = (const float*)d_in[2];  // [E, DFF]
    const float* W2 = (const float*)d_in[3];  // [E, DFF, H]
    const float* b2 = (const float*)d_in[4];  // [E, H]
    float* out = (float*)d_out;               // [W, E, C, H]

    // GEMM1 + bias + gelu -> g_h   (M=2048, N=4096, K=1024 per batch z)
    dim3 grid1(Dff / 128, Cn / 128, Wn * En);
    moe_gemm<Hn, Dff, /*GELU=*/true, /*A_SCR=*/false, /*C_SCR=*/true>
        <<<grid1, 256>>>(x, W1, b1, nullptr);

    // GEMM2 + bias -> out          (M=2048, N=1024, K=4096 per batch z)
    dim3 grid2(Hn / 128, Cn / 128, Wn * En);
    moe_gemm<Dff, Hn, /*GELU=*/false, /*A_SCR=*/true, /*C_SCR=*/false>
        <<<grid2, 256>>>(nullptr, W2, b2, out);
}